// round 1
// baseline (speedup 1.0000x reference)
#include <cuda_runtime.h>

#define K_CODES 2048
#define DIM     256
#define NVEC    65536          // 64*32*32 vectors
#define QELEMS  16777216       // 64*256*1024 output elements
#define HW      1024           // 32*32

// ---------------- scratch (no allocations allowed) ----------------
__device__ int    g_idx[NVEC];
__device__ float  g_sx[NVEC];
__device__ float  g_sc[K_CODES];
__device__ float  g_cbT[DIM * K_CODES];   // codebook transposed [d][k]
__device__ int    g_counts[K_CODES];
__device__ double g_loss;

// ---------------- init: zero accumulators every launch ----------------
__global__ void k_init() {
    int t = blockIdx.x * blockDim.x + threadIdx.x;
    if (t < K_CODES) g_counts[t] = 0;
    if (t == 0) g_loss = 0.0;
}

// ---------------- codebook transpose  [k][d] -> [d][k] ----------------
__global__ void k_prep_cbT(const float* __restrict__ cb) {
    int e = blockIdx.x * blockDim.x + threadIdx.x;   // 0 .. 524287
    int k = e >> 8, d = e & 255;
    g_cbT[d * K_CODES + k] = cb[e];
}

// ---------------- s_c[k] = sum_d c^2  (mul then add, sequential) ------
__global__ void k_prep_sc(const float* __restrict__ cb) {
    int k = blockIdx.x * blockDim.x + threadIdx.x;   // 0..2047
    const float* r = cb + k * DIM;
    float s = 0.f;
    for (int d = 0; d < DIM; d++) s = __fadd_rn(s, __fmul_rn(r[d], r[d]));
    g_sc[k] = s;
}

// ---------------- s_x[n] = sum_d x^2  (sequential ascending d) --------
__global__ void k_prep_sx(const float* __restrict__ x) {
    int bid = blockIdx.x;                 // 256 blocks of 256 threads
    int b   = bid >> 2;
    int hw  = ((bid & 3) << 8) + threadIdx.x;
    const float* p = x + (size_t)b * DIM * HW + hw;
    float s = 0.f;
    for (int d = 0; d < DIM; d++) {
        float v = p[d * HW];
        s = __fadd_rn(s, __fmul_rn(v, v));
    }
    g_sx[(b << 10) + hw] = s;
}

// ---------------- packed f32x2 helpers (FFMA2) ----------------
__device__ __forceinline__ unsigned long long dup2(float v) {
    unsigned long long r;
    asm("mov.b64 %0, {%1, %1};" : "=l"(r) : "f"(v));
    return r;
}
__device__ __forceinline__ void fma2(unsigned long long& acc,
                                     unsigned long long a, unsigned long long b) {
    asm("fma.rn.f32x2 %0, %1, %2, %3;" : "=l"(acc) : "l"(a), "l"(b), "l"(acc));
}
__device__ __forceinline__ void unpack2(unsigned long long v, float& lo, float& hi) {
    asm("mov.b64 {%0, %1}, %2;" : "=f"(lo), "=f"(hi) : "l"(v));
}

// ---------------- main fused GEMM + argmin ----------------
// Block: 64 rows (n), loops over 16 k-tiles of 128 codes, full D=256 in smem.
// Threads 256 = 8 warps; warp owns 8 n's, lane owns 4 k's.
__launch_bounds__(256, 1)
__global__ void k_main(const float* __restrict__ x) {
    extern __shared__ float smem[];
    float4* A4 = (float4*)smem;                    // [256][16] float4 : (d, n)
    float4* B4 = (float4*)(smem + DIM * 64);       // [256][32] float4 : (d, k)

    const int tid = threadIdx.x, lane = tid & 31, warp = tid >> 5;
    const int n0  = blockIdx.x * 64;
    const int b   = n0 >> 10, hw0 = n0 & 1023;

    // ---- load A tile once: x[b][d][hw0..hw0+63], coalesced float4 ----
    const float4* xg = (const float4*)(x + (size_t)b * DIM * HW + hw0);
#pragma unroll
    for (int i = 0; i < 16; i++) {
        int f = i * 256 + tid;            // f = d*16 + nl4
        int d = f >> 4, nl4 = f & 15;
        A4[f] = xg[d * (HW / 4) + nl4];
    }

    float sxr[8];
#pragma unroll
    for (int i = 0; i < 8; i++) sxr[i] = __ldg(&g_sx[n0 + warp * 8 + i]);

    float minv[8]; int mini[8];
#pragma unroll
    for (int i = 0; i < 8; i++) { minv[i] = 3.4e38f; mini[i] = 0; }

    const float4* cbT4 = (const float4*)g_cbT;

    for (int kt = 0; kt < 16; kt++) {
        __syncthreads();
        // ---- load B tile: cbT[d][kt*128 .. +127], coalesced, conflict-free ----
#pragma unroll
        for (int i = 0; i < 32; i++) {
            int f = i * 256 + tid;        // f = d*32 + k4
            int d = f >> 5, k4 = f & 31;
            B4[f] = cbT4[d * (K_CODES / 4) + kt * 32 + k4];
        }
        __syncthreads();

        unsigned long long acc[4][4];     // [n-pair][k] packed f32x2
#pragma unroll
        for (int p = 0; p < 4; p++)
#pragma unroll
            for (int j = 0; j < 4; j++) acc[p][j] = 0ull;

        const ulonglong2* A2 = (const ulonglong2*)A4;
#pragma unroll 8
        for (int d = 0; d < DIM; d++) {
            ulonglong2 aA = A2[d * 16 + warp * 2];      // n pairs (0,1),(2,3)
            ulonglong2 aB = A2[d * 16 + warp * 2 + 1];  // n pairs (4,5),(6,7)
            float4 bf = B4[d * 32 + lane];
            unsigned long long b0 = dup2(bf.x), b1 = dup2(bf.y),
                               b2 = dup2(bf.z), b3 = dup2(bf.w);
            fma2(acc[0][0], aA.x, b0); fma2(acc[0][1], aA.x, b1);
            fma2(acc[0][2], aA.x, b2); fma2(acc[0][3], aA.x, b3);
            fma2(acc[1][0], aA.y, b0); fma2(acc[1][1], aA.y, b1);
            fma2(acc[1][2], aA.y, b2); fma2(acc[1][3], aA.y, b3);
            fma2(acc[2][0], aB.x, b0); fma2(acc[2][1], aB.x, b1);
            fma2(acc[2][2], aB.x, b2); fma2(acc[2][3], aB.x, b3);
            fma2(acc[3][0], aB.y, b0); fma2(acc[3][1], aB.y, b1);
            fma2(acc[3][2], aB.y, b2); fma2(acc[3][3], aB.y, b3);
        }

        // ---- epilogue: dist = fl(fl(sx+sc) - fl(2*dot)); strict < keeps lowest k ----
        int kbase = kt * 128 + lane * 4;
        float sck[4];
#pragma unroll
        for (int j = 0; j < 4; j++) sck[j] = __ldg(&g_sc[kbase + j]);
#pragma unroll
        for (int p = 0; p < 4; p++) {
            int i0 = p * 2, i1 = p * 2 + 1;
#pragma unroll
            for (int j = 0; j < 4; j++) {
                float dlo, dhi; unpack2(acc[p][j], dlo, dhi);
                float u0 = __fadd_rn(sxr[i0], sck[j]);
                float t0 = __fmul_rn(2.0f, dlo);
                float dist0 = __fadd_rn(u0, -t0);
                if (dist0 < minv[i0]) { minv[i0] = dist0; mini[i0] = kbase + j; }
                float u1 = __fadd_rn(sxr[i1], sck[j]);
                float t1 = __fmul_rn(2.0f, dhi);
                float dist1 = __fadd_rn(u1, -t1);
                if (dist1 < minv[i1]) { minv[i1] = dist1; mini[i1] = kbase + j; }
            }
        }
    }

    // ---- cross-lane reduce: min value, ties -> lowest index ----
#pragma unroll
    for (int i = 0; i < 8; i++) {
        float v = minv[i]; int id = mini[i];
        for (int off = 16; off; off >>= 1) {
            float ov = __shfl_down_sync(0xffffffffu, v, off);
            int   oi = __shfl_down_sync(0xffffffffu, id, off);
            if (ov < v || (ov == v && oi < id)) { v = ov; id = oi; }
        }
        if (lane == 0) {
            int n = n0 + warp * 8 + i;
            g_idx[n] = id;
            atomicAdd(&g_counts[id], 1);
        }
    }
}

// ---------------- quant gather + loss accumulation ----------------
__global__ void k_out(const float* __restrict__ x, const float* __restrict__ cb,
                      float* __restrict__ outq) {
    unsigned int stride = gridDim.x * blockDim.x;
    unsigned int e0 = blockIdx.x * blockDim.x + threadIdx.x;
    double ls = 0.0;
    for (unsigned int e = e0; e < QELEMS; e += stride) {
        int hw = (int)(e & 1023);
        int d  = (int)((e >> 10) & 255);
        int b  = (int)(e >> 18);
        int n  = (b << 10) + hw;
        int k  = g_idx[n];
        float q  = __ldg(&cb[k * DIM + d]);
        float xv = x[e];
        outq[e] = q;
        float df = __fadd_rn(q, -xv);
        ls += (double)__fmul_rn(df, df);
    }
    for (int off = 16; off; off >>= 1) ls += __shfl_down_sync(0xffffffffu, ls, off);
    __shared__ double ws[8];
    if ((threadIdx.x & 31) == 0) ws[threadIdx.x >> 5] = ls;
    __syncthreads();
    if (threadIdx.x == 0) {
        double s = 0.0;
        for (int i = 0; i < 8; i++) s += ws[i];
        atomicAdd(&g_loss, s);
    }
}

// ---------------- idx -> float tail ----------------
__global__ void k_idxout(float* __restrict__ oidx) {
    int t = blockIdx.x * blockDim.x + threadIdx.x;
    if (t < NVEC) oidx[t] = (float)g_idx[t];
}

// ---------------- scalars: loss & perplexity ----------------
__global__ void k_fin(float* __restrict__ o_loss, float* __restrict__ o_perp) {
    __shared__ double ws[8];
    int tid = threadIdx.x;
    double s = 0.0;
    for (int k = tid; k < K_CODES; k += 256) {
        float p = (float)g_counts[k] / 65536.0f;   // exact (pow2 divide)
        float l = logf(__fadd_rn(p, 1e-10f));
        s += (double)__fmul_rn(p, l);
    }
    for (int off = 16; off; off >>= 1) s += __shfl_down_sync(0xffffffffu, s, off);
    if ((tid & 31) == 0) ws[tid >> 5] = s;
    __syncthreads();
    if (tid == 0) {
        double tot = 0.0;
        for (int i = 0; i < 8; i++) tot += ws[i];
        *o_perp = expf(-(float)tot);
        float m = (float)(g_loss / (double)QELEMS);
        *o_loss = __fadd_rn(m, __fmul_rn(0.25f, m));   // m + 0.25*m, ref order
    }
}

// ---------------- launch ----------------
extern "C" void kernel_launch(void* const* d_in, const int* in_sizes, int n_in,
                              void* d_out, int out_size) {
    const float* x  = (const float*)d_in[0];
    const float* cb = (const float*)d_in[1];
    if (n_in >= 2 && in_sizes[0] == K_CODES * DIM && in_sizes[1] == QELEMS) {
        x = (const float*)d_in[1]; cb = (const float*)d_in[0];   // reversed order guard
    }
    float* out = (float*)d_out;

    // Output layout: [loss | quant(16777216) | perplexity | idx(65536)] as f32.
    float* o_loss  = out;
    float* o_quant = out + 1;
    float* o_perp  = out + 1 + QELEMS;
    float* o_idx   = out + 2 + QELEMS;
    if (out_size == QELEMS) {            // fallback: only quant requested
        o_quant = out; o_loss = nullptr; o_perp = nullptr; o_idx = nullptr;
    }

    cudaFuncSetAttribute(k_main, cudaFuncAttributeMaxDynamicSharedMemorySize, 196608);

    k_init    <<<8,    256>>>();
    k_prep_cbT<<<2048, 256>>>(cb);
    k_prep_sc <<<8,    256>>>(cb);
    k_prep_sx <<<256,  256>>>(x);
    k_main    <<<1024, 256, 196608>>>(x);
    k_out     <<<4096, 256>>>(x, cb, o_quant);
    if (o_idx)  k_idxout<<<256, 256>>>(o_idx);
    if (o_loss) k_fin   <<<1,   256>>>(o_loss, o_perp);
}

// round 7
// speedup vs baseline: 2.0923x; 2.0923x over previous
#include <cuda_runtime.h>
#include <cuda_bf16.h>
#include <cstdint>

#define K_CODES 2048
#define DIM     256
#define NVEC    65536          // 64*32*32 vectors
#define QELEMS  16777216       // 64*256*1024 output elements
#define HW      1024           // 32*32

// ---------------- scratch (no allocations allowed) ----------------
__device__ int            g_idx[NVEC];
__device__ float          g_sx[NVEC];
__device__ float          g_sc[K_CODES];
__device__ __nv_bfloat16  g_cbh[K_CODES * DIM];   // codebook bf16 high part
__device__ __nv_bfloat16  g_cbl[K_CODES * DIM];   // codebook bf16 low  part
__device__ int            g_counts[K_CODES];
__device__ double         g_loss;

// ---------------- init ----------------
__global__ void k_init() {
    int t = blockIdx.x * blockDim.x + threadIdx.x;
    if (t < K_CODES) g_counts[t] = 0;
    if (t == 0) g_loss = 0.0;
}

// ---------------- codebook bf16 split ----------------
__global__ void k_prep_split(const float* __restrict__ cb) {
    int e = blockIdx.x * blockDim.x + threadIdx.x;   // 0..524287
    float v = cb[e];
    __nv_bfloat16 h = __float2bfloat16(v);
    g_cbh[e] = h;
    g_cbl[e] = __float2bfloat16(v - __bfloat162float(h));
}

// ---------------- s_c[k] = sum_d c^2 (sequential, bit-stable) ----------------
__global__ void k_prep_sc(const float* __restrict__ cb) {
    int k = blockIdx.x * blockDim.x + threadIdx.x;
    const float* r = cb + k * DIM;
    float s = 0.f;
    for (int d = 0; d < DIM; d++) s = __fadd_rn(s, __fmul_rn(r[d], r[d]));
    g_sc[k] = s;
}

// ---------------- s_x[n] = sum_d x^2 (sequential ascending d) ----------------
__global__ void k_prep_sx(const float* __restrict__ x) {
    int bid = blockIdx.x;
    int b   = bid >> 2;
    int hw  = ((bid & 3) << 8) + threadIdx.x;
    const float* p = x + (size_t)b * DIM * HW + hw;
    float s = 0.f;
    for (int d = 0; d < DIM; d++) {
        float v = p[d * HW];
        s = __fadd_rn(s, __fmul_rn(v, v));
    }
    g_sx[(b << 10) + hw] = s;
}

// ================== sm_80-era PTX helpers (legal on compute_100) ==================
__device__ __forceinline__ uint32_t smem_u32(const void* p) {
    uint32_t a;
    asm("{ .reg .u64 t; cvta.to.shared.u64 t, %1; cvt.u32.u64 %0, t; }" : "=r"(a) : "l"(p));
    return a;
}
__device__ __forceinline__ void ldsm4(uint32_t& r0, uint32_t& r1, uint32_t& r2, uint32_t& r3,
                                      uint32_t addr) {
    asm volatile("ldmatrix.sync.aligned.m8n8.x4.shared.b16 {%0,%1,%2,%3}, [%4];"
                 : "=r"(r0), "=r"(r1), "=r"(r2), "=r"(r3) : "r"(addr));
}
__device__ __forceinline__ void mma16816(float* c,
                                         uint32_t a0, uint32_t a1, uint32_t a2, uint32_t a3,
                                         uint32_t b0, uint32_t b1) {
    asm volatile(
        "mma.sync.aligned.m16n8k16.row.col.f32.bf16.bf16.f32 "
        "{%0,%1,%2,%3}, {%4,%5,%6,%7}, {%8,%9}, {%0,%1,%2,%3};"
        : "+f"(c[0]), "+f"(c[1]), "+f"(c[2]), "+f"(c[3])
        : "r"(a0), "r"(a1), "r"(a2), "r"(a3), "r"(b0), "r"(b1));
}
__device__ __forceinline__ void cp16(uint32_t dst, const void* src) {
    asm volatile("cp.async.cg.shared.global [%0], [%1], 16;" :: "r"(dst), "l"(src));
}
#define CP_COMMIT() asm volatile("cp.async.commit_group;" ::: "memory")
#define CP_WAIT0()  asm volatile("cp.async.wait_group 0;"  ::: "memory")
#define CP_WAIT1()  asm volatile("cp.async.wait_group 1;"  ::: "memory")

// ---------------- SMEM layout (bytes) ----------------
#define OFF_AH   0          // 65536 : A hi, 128 rows x 512B (256 d bf16), swizzled
#define OFF_AL   65536      // 65536 : A lo
#define OFF_B    131072     // 2 bufs x 32768 : per buf {B hi 16384 | B lo 16384}
#define OFF_SC   196608     // 8192  : sc[2048] f32
#define OFF_RED  204800     // 1024 f32 minv[2][128] + 1024 i32 mini[2][128]
#define SMEM_TOTAL 206848

// swizzle: 16B-chunk c within 512B row r: phys chunk = c ^ (r&7)
__device__ __forceinline__ uint32_t swz(int r, int c) {
    return (uint32_t)r * 512u + (uint32_t)((c ^ (r & 7)) << 4);
}

// ---------------- main: HMMA distance GEMM + fused argmin ----------------
__launch_bounds__(256, 1)
__global__ void k_main3(const float* __restrict__ x) {
    extern __shared__ char smem[];
    const uint32_t sb = smem_u32(smem);
    const int tid  = threadIdx.x, lane = tid & 31, warp = tid >> 5;
    const int wm   = warp >> 1, wn = warp & 1;           // 4 warps in M, 2 in N

    const int n0  = blockIdx.x * 128;
    const int b   = n0 >> 10, hw0 = n0 & 1023;

    float* sc_sm = (float*)(smem + OFF_SC);

    // ---- per-thread B-load addressing (8 chunks of 16B per tile) ----
    uint32_t bdst[8];
    const __nv_bfloat16* bsrc[8];
#pragma unroll
    for (int i = 0; i < 8; i++) {
        int c = tid + i * 256;                  // 0..2047
        int arr = c >> 10, c2 = c & 1023, row = c2 >> 5, ch = c2 & 31;
        bdst[i] = (uint32_t)OFF_B + (uint32_t)arr * 16384u + swz(row, ch);
        bsrc[i] = (arr ? g_cbl : g_cbh) + (row << 8) + (ch << 3);
    }

    // ---- prefetch B tile 0 into buf 0 ----
#pragma unroll
    for (int i = 0; i < 8; i++) cp16(sb + bdst[i], bsrc[i]);
    CP_COMMIT();

    // ---- sc -> smem ----
#pragma unroll
    for (int c = tid; c < K_CODES; c += 256) sc_sm[c] = __ldg(&g_sc[c]);

    // ---- A load + bf16 split -> smem (swizzled) ----
    {
        int r = tid & 127, hf = tid >> 7, r7 = r & 7;
        const float* px = x + (size_t)b * DIM * HW + hw0 + r;
        char* rowh = smem + OFF_AH + r * 512;
        char* rowl = smem + OFF_AL + r * 512;
#pragma unroll 4
        for (int d = hf * 128; d < hf * 128 + 128; d += 2) {
            float v0 = __ldg(px + (size_t)d * HW);
            float v1 = __ldg(px + (size_t)(d + 1) * HW);
            __nv_bfloat16 h0 = __float2bfloat16(v0), h1 = __float2bfloat16(v1);
            float l0 = v0 - __bfloat162float(h0);
            float l1 = v1 - __bfloat162float(h1);
            __nv_bfloat162 hp = __halves2bfloat162(h0, h1);
            __nv_bfloat162 lp = __halves2bfloat162(__float2bfloat16(l0), __float2bfloat16(l1));
            uint32_t off = (uint32_t)((((d >> 3) ^ r7) << 4) | ((d & 7) << 1));
            *(uint32_t*)(rowh + off) = *(uint32_t*)&hp;
            *(uint32_t*)(rowl + off) = *(uint32_t*)&lp;
        }
    }

    // ---- per-lane ldmatrix base addressing ----
    // A m16k16 frag: lane -> row m0+(l&15), k half (l>>4)
    const int aRow = wm * 32 + (lane & 15);
    const int a_r7 = aRow & 7, a_kl = lane >> 4;
    const uint32_t aH0 = sb + OFF_AH + aRow * 512;
    const uint32_t aH1 = aH0 + 16 * 512;
    const uint32_t aL0 = sb + OFF_AL + aRow * 512;
    const uint32_t aL1 = aL0 + 16 * 512;
    // B n16k16 frag: lane -> row n0+(l&7)+8*(l>>4), k half (l>>3)&1
    const int bRow = wn * 16 + (lane & 7) + ((lane >> 4) << 3);
    const int b_r7 = bRow & 7, b_kl = (lane >> 3) & 1;
    const uint32_t bRowOff = (uint32_t)bRow * 512u;

    // ---- per-thread argmin state: rows wm*32 + i*8 + (lane>>2), i=0..3 ----
    float sxr[4];
#pragma unroll
    for (int i = 0; i < 4; i++)
        sxr[i] = __ldg(&g_sx[n0 + wm * 32 + i * 8 + (lane >> 2)]);
    float minv[4]; int mink[4];
#pragma unroll
    for (int i = 0; i < 4; i++) { minv[i] = 3.4e38f; mink[i] = 0; }

    __syncthreads();    // A tile + sc visible

    for (int t = 0; t < 64; t++) {
        const int buf = t & 1;
        if (t < 63) {
            const uint32_t db = sb + (uint32_t)((buf ^ 1) * 32768);
            const int adv = (t + 1) * 8192;     // 32 codes * 256 d per tile
#pragma unroll
            for (int i = 0; i < 8; i++) cp16(db + bdst[i], bsrc[i] + adv);
            CP_COMMIT();
            CP_WAIT1();
        } else {
            CP_WAIT0();
        }
        __syncthreads();                        // tile t fully resident

        float acc[2][2][4];
#pragma unroll
        for (int mt = 0; mt < 2; mt++)
#pragma unroll
            for (int nt = 0; nt < 2; nt++)
#pragma unroll
                for (int j = 0; j < 4; j++) acc[mt][nt][j] = 0.f;

        const uint32_t bH = sb + (uint32_t)OFF_B + (uint32_t)(buf * 32768) + bRowOff;  // FIXED: +OFF_B
        const uint32_t bL = bH + 16384;

#pragma unroll
        for (int kc = 0; kc < 16; kc++) {
            const uint32_t aoff = (uint32_t)(((2 * kc + a_kl) ^ a_r7) << 4);
            const uint32_t boff = (uint32_t)(((2 * kc + b_kl) ^ b_r7) << 4);
            uint32_t ah0, ah1, ah2, ah3, ah4, ah5, ah6, ah7;
            uint32_t al0, al1, al2, al3, al4, al5, al6, al7;
            uint32_t bh0, bh1, bh2, bh3, bl0, bl1, bl2, bl3;
            ldsm4(ah0, ah1, ah2, ah3, aH0 + aoff);
            ldsm4(ah4, ah5, ah6, ah7, aH1 + aoff);
            ldsm4(bh0, bh1, bh2, bh3, bH + boff);
            ldsm4(al0, al1, al2, al3, aL0 + aoff);
            ldsm4(al4, al5, al6, al7, aL1 + aoff);
            ldsm4(bl0, bl1, bl2, bl3, bL + boff);
            // xh*ch
            mma16816(acc[0][0], ah0, ah1, ah2, ah3, bh0, bh1);
            mma16816(acc[0][1], ah0, ah1, ah2, ah3, bh2, bh3);
            mma16816(acc[1][0], ah4, ah5, ah6, ah7, bh0, bh1);
            mma16816(acc[1][1], ah4, ah5, ah6, ah7, bh2, bh3);
            // xh*cl
            mma16816(acc[0][0], ah0, ah1, ah2, ah3, bl0, bl1);
            mma16816(acc[0][1], ah0, ah1, ah2, ah3, bl2, bl3);
            mma16816(acc[1][0], ah4, ah5, ah6, ah7, bl0, bl1);
            mma16816(acc[1][1], ah4, ah5, ah6, ah7, bl2, bl3);
            // xl*ch
            mma16816(acc[0][0], al0, al1, al2, al3, bh0, bh1);
            mma16816(acc[0][1], al0, al1, al2, al3, bh2, bh3);
            mma16816(acc[1][0], al4, al5, al6, al7, bh0, bh1);
            mma16816(acc[1][1], al4, al5, al6, al7, bh2, bh3);
        }

        // ---- fused argmin epilogue: dist = fl(fl(sx+sc) - fl(2*dot)) ----
        const int kbw = (t << 5) + wn * 16 + ((lane & 3) << 1);
#pragma unroll
        for (int mt = 0; mt < 2; mt++)
#pragma unroll
            for (int half = 0; half < 2; half++) {
                const int i = mt * 2 + half;
                const float sx_i = sxr[i];
#pragma unroll
                for (int nt = 0; nt < 2; nt++) {
                    const int c0 = kbw + nt * 8;
                    float v0 = acc[mt][nt][half * 2 + 0];
                    float v1 = acc[mt][nt][half * 2 + 1];
                    float u0 = __fadd_rn(sx_i, sc_sm[c0]);
                    float d0 = __fadd_rn(u0, -__fmul_rn(2.0f, v0));
                    if (d0 < minv[i]) { minv[i] = d0; mink[i] = c0; }
                    float u1 = __fadd_rn(sx_i, sc_sm[c0 + 1]);
                    float d1 = __fadd_rn(u1, -__fmul_rn(2.0f, v1));
                    if (d1 < minv[i]) { minv[i] = d1; mink[i] = c0 + 1; }
                }
            }
        __syncthreads();                        // compute(t) done before buf overwrite
    }

    // ---- cross-lane (groups of 4 share a row), then cross-wn merge ----
    float* fred = (float*)(smem + OFF_RED);
    int*   ired = (int*)(smem + OFF_RED + 1024);
#pragma unroll
    for (int i = 0; i < 4; i++) {
        float v = minv[i]; int id = mink[i];
#pragma unroll
        for (int off = 1; off <= 2; off <<= 1) {
            float ov = __shfl_xor_sync(0xffffffffu, v, off);
            int   oi = __shfl_xor_sync(0xffffffffu, id, off);
            if (ov < v || (ov == v && oi < id)) { v = ov; id = oi; }
        }
        if ((lane & 3) == 0) {
            int r = wm * 32 + i * 8 + (lane >> 2);
            fred[wn * 128 + r] = v;
            ired[wn * 128 + r] = id;
        }
    }
    __syncthreads();
    if (tid < 128) {
        float va = fred[tid], vb = fred[128 + tid];
        int   ia = ired[tid], ib = ired[128 + tid];
        int k = (vb < va || (vb == va && ib < ia)) ? ib : ia;
        g_idx[n0 + tid] = k;
        atomicAdd(&g_counts[k], 1);
    }
}

// ---------------- quant gather + loss accumulation ----------------
__global__ void k_out(const float* __restrict__ x, const float* __restrict__ cb,
                      float* __restrict__ outq) {
    unsigned int stride = gridDim.x * blockDim.x;
    unsigned int e0 = blockIdx.x * blockDim.x + threadIdx.x;
    double ls = 0.0;
    for (unsigned int e = e0; e < QELEMS; e += stride) {
        int hw = (int)(e & 1023);
        int d  = (int)((e >> 10) & 255);
        int b  = (int)(e >> 18);
        int n  = (b << 10) + hw;
        int k  = g_idx[n];
        float q  = __ldg(&cb[k * DIM + d]);
        float xv = x[e];
        outq[e] = q;
        float df = __fadd_rn(q, -xv);
        ls += (double)__fmul_rn(df, df);
    }
    for (int off = 16; off; off >>= 1) ls += __shfl_down_sync(0xffffffffu, ls, off);
    __shared__ double ws[8];
    if ((threadIdx.x & 31) == 0) ws[threadIdx.x >> 5] = ls;
    __syncthreads();
    if (threadIdx.x == 0) {
        double s = 0.0;
        for (int i = 0; i < 8; i++) s += ws[i];
        atomicAdd(&g_loss, s);
    }
}

// ---------------- idx -> float tail ----------------
__global__ void k_idxout(float* __restrict__ oidx) {
    int t = blockIdx.x * blockDim.x + threadIdx.x;
    if (t < NVEC) oidx[t] = (float)g_idx[t];
}

// ---------------- scalars: loss & perplexity ----------------
__global__ void k_fin(float* __restrict__ o_loss, float* __restrict__ o_perp) {
    __shared__ double ws[8];
    int tid = threadIdx.x;
    double s = 0.0;
    for (int k = tid; k < K_CODES; k += 256) {
        float p = (float)g_counts[k] / 65536.0f;
        float l = logf(__fadd_rn(p, 1e-10f));
        s += (double)__fmul_rn(p, l);
    }
    for (int off = 16; off; off >>= 1) s += __shfl_down_sync(0xffffffffu, s, off);
    if ((tid & 31) == 0) ws[tid >> 5] = s;
    __syncthreads();
    if (tid == 0) {
        double tot = 0.0;
        for (int i = 0; i < 8; i++) tot += ws[i];
        *o_perp = expf(-(float)tot);
        float m = (float)(g_loss / (double)QELEMS);
        *o_loss = __fadd_rn(m, __fmul_rn(0.25f, m));
    }
}

// ---------------- launch ----------------
extern "C" void kernel_launch(void* const* d_in, const int* in_sizes, int n_in,
                              void* d_out, int out_size) {
    const float* x  = (const float*)d_in[0];
    const float* cb = (const float*)d_in[1];
    if (n_in >= 2 && in_sizes[0] == K_CODES * DIM && in_sizes[1] == QELEMS) {
        x = (const float*)d_in[1]; cb = (const float*)d_in[0];
    }
    float* out = (float*)d_out;

    float* o_loss  = out;
    float* o_quant = out + 1;
    float* o_perp  = out + 1 + QELEMS;
    float* o_idx   = out + 2 + QELEMS;
    if (out_size == QELEMS) {
        o_quant = out; o_loss = nullptr; o_perp = nullptr; o_idx = nullptr;
    }

    cudaFuncSetAttribute(k_main3, cudaFuncAttributeMaxDynamicSharedMemorySize, SMEM_TOTAL);

    k_init      <<<8,    256>>>();
    k_prep_split<<<2048, 256>>>(cb);
    k_prep_sc   <<<8,    256>>>(cb);
    k_prep_sx   <<<256,  256>>>(x);
    k_main3     <<<512,  256, SMEM_TOTAL>>>(x);
    k_out       <<<4096, 256>>>(x, cb, o_quant);
    if (o_idx)  k_idxout<<<256, 256>>>(o_idx);
    if (o_loss) k_fin   <<<1,   256>>>(o_loss, o_perp);
}

// round 9
// speedup vs baseline: 2.4088x; 1.1513x over previous
#include <cuda_runtime.h>
#include <cuda_bf16.h>
#include <cstdint>

#define K_CODES 2048
#define DIM     256
#define NVEC    65536          // 64*32*32 vectors
#define QELEMS  16777216       // 64*256*1024 output elements
#define HW      1024           // 32*32

// ---------------- scratch (no allocations allowed) ----------------
__device__ unsigned long long g_best[NVEC];       // packed (dist_bits<<32 | k)
__device__ float          g_sx[NVEC];
__device__ float          g_sc[K_CODES];
__device__ __nv_bfloat16  g_cbh[K_CODES * DIM];   // codebook bf16 high part
__device__ __nv_bfloat16  g_cbl[K_CODES * DIM];   // codebook bf16 low  part
__device__ int            g_counts[K_CODES];
__device__ double         g_loss;

// ---------------- init ----------------
__global__ void k_init() {
    int t = blockIdx.x * blockDim.x + threadIdx.x;   // 256x256 = 65536
    if (t < K_CODES) g_counts[t] = 0;
    g_best[t] = 0xFFFFFFFFFFFFFFFFull;
    if (t == 0) g_loss = 0.0;
}

// ---------------- codebook bf16 split ----------------
__global__ void k_prep_split(const float* __restrict__ cb) {
    int e = blockIdx.x * blockDim.x + threadIdx.x;   // 0..524287
    float v = cb[e];
    __nv_bfloat16 h = __float2bfloat16(v);
    g_cbh[e] = h;
    g_cbl[e] = __float2bfloat16(v - __bfloat162float(h));
}

// ---------------- s_c[k] = sum_d c^2 (sequential, bit-stable) ----------------
__global__ void k_prep_sc(const float* __restrict__ cb) {
    int k = blockIdx.x * blockDim.x + threadIdx.x;
    const float* r = cb + k * DIM;
    float s = 0.f;
    for (int d = 0; d < DIM; d++) s = __fadd_rn(s, __fmul_rn(r[d], r[d]));
    g_sc[k] = s;
}

// ---------------- s_x[n] = sum_d x^2 (sequential ascending d) ----------------
__global__ void k_prep_sx(const float* __restrict__ x) {
    int bid = blockIdx.x;
    int b   = bid >> 2;
    int hw  = ((bid & 3) << 8) + threadIdx.x;
    const float* p = x + (size_t)b * DIM * HW + hw;
    float s = 0.f;
    for (int d = 0; d < DIM; d++) {
        float v = p[d * HW];
        s = __fadd_rn(s, __fmul_rn(v, v));
    }
    g_sx[(b << 10) + hw] = s;
}

// ================== sm_80-era PTX helpers (legal on compute_100) ==================
__device__ __forceinline__ uint32_t smem_u32(const void* p) {
    uint32_t a;
    asm("{ .reg .u64 t; cvta.to.shared.u64 t, %1; cvt.u32.u64 %0, t; }" : "=r"(a) : "l"(p));
    return a;
}
__device__ __forceinline__ void ldsm4(uint32_t& r0, uint32_t& r1, uint32_t& r2, uint32_t& r3,
                                      uint32_t addr) {
    asm volatile("ldmatrix.sync.aligned.m8n8.x4.shared.b16 {%0,%1,%2,%3}, [%4];"
                 : "=r"(r0), "=r"(r1), "=r"(r2), "=r"(r3) : "r"(addr));
}
__device__ __forceinline__ void mma16816(float* c,
                                         uint32_t a0, uint32_t a1, uint32_t a2, uint32_t a3,
                                         uint32_t b0, uint32_t b1) {
    asm volatile(
        "mma.sync.aligned.m16n8k16.row.col.f32.bf16.bf16.f32 "
        "{%0,%1,%2,%3}, {%4,%5,%6,%7}, {%8,%9}, {%0,%1,%2,%3};"
        : "+f"(c[0]), "+f"(c[1]), "+f"(c[2]), "+f"(c[3])
        : "r"(a0), "r"(a1), "r"(a2), "r"(a3), "r"(b0), "r"(b1));
}
__device__ __forceinline__ void cp16(uint32_t dst, const void* src) {
    asm volatile("cp.async.cg.shared.global [%0], [%1], 16;" :: "r"(dst), "l"(src));
}
#define CP_COMMIT() asm volatile("cp.async.commit_group;" ::: "memory")
#define CP_WAIT0()  asm volatile("cp.async.wait_group 0;"  ::: "memory")
#define CP_WAIT1()  asm volatile("cp.async.wait_group 1;"  ::: "memory")

// ---------------- SMEM layout (bytes) ----------------
#define OFF_AH   0          // 65536 : A hi, 128 rows x 512B (256 d bf16), swizzled
#define OFF_AL   65536      // 65536 : A lo
#define OFF_B    131072     // 2 bufs x 32768 : per buf {B hi 16384 | B lo 16384}
#define OFF_SC   196608     // 4096  : sc[1024] f32 (this CTA's code half)
#define OFF_RED  200704     // 1024 f32 minv[2][128] + 1024 i32 mini[2][128]
#define SMEM_TOTAL 202752

// swizzle: 16B-chunk c within 512B row r: phys chunk = c ^ (r&7)
__device__ __forceinline__ uint32_t swz(int r, int c) {
    return (uint32_t)r * 512u + (uint32_t)((c ^ (r & 7)) << 4);
}

// ---------------- main: HMMA distance GEMM + fused argmin ----------------
// Grid 1024: blockIdx = rb*2 + half. CTA: rows [rb*128, +128) x codes [half*1024, +1024).
__launch_bounds__(256, 1)
__global__ void k_main3(const float* __restrict__ x) {
    extern __shared__ char smem[];
    const uint32_t sb = smem_u32(smem);
    const int tid  = threadIdx.x, lane = tid & 31, warp = tid >> 5;
    const int wm   = warp >> 1, wn = warp & 1;           // 4 warps in M, 2 in N

    const int rb   = blockIdx.x >> 1, half = blockIdx.x & 1;
    const int n0   = rb * 128;
    const int b    = n0 >> 10, hw0 = n0 & 1023;
    const int kofs = half << 10;                          // code-half base

    float* sc_sm = (float*)(smem + OFF_SC);

    // ---- per-thread B-load addressing (8 chunks of 16B per tile) ----
    uint32_t bdst[8];
    const __nv_bfloat16* bsrc[8];
#pragma unroll
    for (int i = 0; i < 8; i++) {
        int c = tid + i * 256;                  // 0..2047
        int arr = c >> 10, c2 = c & 1023, row = c2 >> 5, ch = c2 & 31;
        bdst[i] = (uint32_t)OFF_B + (uint32_t)arr * 16384u + swz(row, ch);
        bsrc[i] = (arr ? g_cbl : g_cbh) + ((kofs + row) << 8) + (ch << 3);
    }

    // ---- prefetch B tile 0 into buf 0 ----
#pragma unroll
    for (int i = 0; i < 8; i++) cp16(sb + bdst[i], bsrc[i]);
    CP_COMMIT();

    // ---- sc (this half) -> smem ----
#pragma unroll
    for (int c = tid; c < 1024; c += 256) sc_sm[c] = __ldg(&g_sc[kofs + c]);

    // ---- A load + bf16 split -> smem (swizzled) ----
    {
        int r = tid & 127, hf = tid >> 7, r7 = r & 7;
        const float* px = x + (size_t)b * DIM * HW + hw0 + r;
        char* rowh = smem + OFF_AH + r * 512;
        char* rowl = smem + OFF_AL + r * 512;
#pragma unroll 4
        for (int d = hf * 128; d < hf * 128 + 128; d += 2) {
            float v0 = __ldg(px + (size_t)d * HW);
            float v1 = __ldg(px + (size_t)(d + 1) * HW);
            __nv_bfloat16 h0 = __float2bfloat16(v0), h1 = __float2bfloat16(v1);
            float l0 = v0 - __bfloat162float(h0);
            float l1 = v1 - __bfloat162float(h1);
            __nv_bfloat162 hp = __halves2bfloat162(h0, h1);
            __nv_bfloat162 lp = __halves2bfloat162(__float2bfloat16(l0), __float2bfloat16(l1));
            uint32_t off = (uint32_t)((((d >> 3) ^ r7) << 4) | ((d & 7) << 1));
            *(uint32_t*)(rowh + off) = *(uint32_t*)&hp;
            *(uint32_t*)(rowl + off) = *(uint32_t*)&lp;
        }
    }

    // ---- per-lane ldmatrix base addressing ----
    const int aRow = wm * 32 + (lane & 15);
    const int a_r7 = aRow & 7, a_kl = lane >> 4;
    const uint32_t aH0 = sb + OFF_AH + aRow * 512;
    const uint32_t aH1 = aH0 + 16 * 512;
    const uint32_t aL0 = sb + OFF_AL + aRow * 512;
    const uint32_t aL1 = aL0 + 16 * 512;
    const int bRow = wn * 16 + (lane & 7) + ((lane >> 4) << 3);
    const int b_r7 = bRow & 7, b_kl = (lane >> 3) & 1;
    const uint32_t bRowOff = (uint32_t)bRow * 512u;

    // ---- per-thread argmin state: rows wm*32 + i*8 + (lane>>2), i=0..3 ----
    float sxr[4];
#pragma unroll
    for (int i = 0; i < 4; i++)
        sxr[i] = __ldg(&g_sx[n0 + wm * 32 + i * 8 + (lane >> 2)]);
    float minv[4]; int mink[4];
#pragma unroll
    for (int i = 0; i < 4; i++) { minv[i] = 3.4e38f; mink[i] = 0; }

    __syncthreads();    // A tile + sc visible

    uint32_t fah[2][8], fal[2][8], fbh[2][4], fbl[2][4];

#define LOAD_FRAGS(s, kc) do {                                                   \
        const uint32_t aoff_ = (uint32_t)(((2 * (kc) + a_kl) ^ a_r7) << 4);      \
        const uint32_t boff_ = (uint32_t)(((2 * (kc) + b_kl) ^ b_r7) << 4);      \
        ldsm4(fah[s][0], fah[s][1], fah[s][2], fah[s][3], aH0 + aoff_);          \
        ldsm4(fah[s][4], fah[s][5], fah[s][6], fah[s][7], aH1 + aoff_);          \
        ldsm4(fbh[s][0], fbh[s][1], fbh[s][2], fbh[s][3], bH + boff_);           \
        ldsm4(fal[s][0], fal[s][1], fal[s][2], fal[s][3], aL0 + aoff_);          \
        ldsm4(fal[s][4], fal[s][5], fal[s][6], fal[s][7], aL1 + aoff_);          \
        ldsm4(fbl[s][0], fbl[s][1], fbl[s][2], fbl[s][3], bL + boff_);           \
    } while (0)

#define DO_MMAS(s) do {                                                          \
        mma16816(acc[0][0], fah[s][0], fah[s][1], fah[s][2], fah[s][3], fbh[s][0], fbh[s][1]); \
        mma16816(acc[0][1], fah[s][0], fah[s][1], fah[s][2], fah[s][3], fbh[s][2], fbh[s][3]); \
        mma16816(acc[1][0], fah[s][4], fah[s][5], fah[s][6], fah[s][7], fbh[s][0], fbh[s][1]); \
        mma16816(acc[1][1], fah[s][4], fah[s][5], fah[s][6], fah[s][7], fbh[s][2], fbh[s][3]); \
        mma16816(acc[0][0], fah[s][0], fah[s][1], fah[s][2], fah[s][3], fbl[s][0], fbl[s][1]); \
        mma16816(acc[0][1], fah[s][0], fah[s][1], fah[s][2], fah[s][3], fbl[s][2], fbl[s][3]); \
        mma16816(acc[1][0], fah[s][4], fah[s][5], fah[s][6], fah[s][7], fbl[s][0], fbl[s][1]); \
        mma16816(acc[1][1], fah[s][4], fah[s][5], fah[s][6], fah[s][7], fbl[s][2], fbl[s][3]); \
        mma16816(acc[0][0], fal[s][0], fal[s][1], fal[s][2], fal[s][3], fbh[s][0], fbh[s][1]); \
        mma16816(acc[0][1], fal[s][0], fal[s][1], fal[s][2], fal[s][3], fbh[s][2], fbh[s][3]); \
        mma16816(acc[1][0], fal[s][4], fal[s][5], fal[s][6], fal[s][7], fbh[s][0], fbh[s][1]); \
        mma16816(acc[1][1], fal[s][4], fal[s][5], fal[s][6], fal[s][7], fbh[s][2], fbh[s][3]); \
    } while (0)

    for (int t = 0; t < 32; t++) {
        const int buf = t & 1;
        if (t < 31) {
            const uint32_t db = sb + (uint32_t)((buf ^ 1) * 32768);
            const int adv = (t + 1) * 8192;     // 32 codes * 256 d per tile
#pragma unroll
            for (int i = 0; i < 8; i++) cp16(db + bdst[i], bsrc[i] + adv);
            CP_COMMIT();
            CP_WAIT1();
        } else {
            CP_WAIT0();
        }
        __syncthreads();                        // tile t fully resident

        float acc[2][2][4];
#pragma unroll
        for (int mt = 0; mt < 2; mt++)
#pragma unroll
            for (int nt = 0; nt < 2; nt++)
#pragma unroll
                for (int j = 0; j < 4; j++) acc[mt][nt][j] = 0.f;

        const uint32_t bH = sb + (uint32_t)OFF_B + (uint32_t)(buf * 32768) + bRowOff;
        const uint32_t bL = bH + 16384;

        // 2-stage software-pipelined fragment loads
        LOAD_FRAGS(0, 0);
#pragma unroll
        for (int kc = 0; kc < 16; kc++) {
            const int cur = kc & 1;
            if (kc < 15) LOAD_FRAGS(cur ^ 1, kc + 1);
            DO_MMAS(cur);
        }

        // ---- fused argmin epilogue: dist = fl(fl(sx+sc) - fl(2*dot)) ----
        const int kbw = (t << 5) + wn * 16 + ((lane & 3) << 1);   // local code idx
#pragma unroll
        for (int mt = 0; mt < 2; mt++)
#pragma unroll
            for (int hhalf = 0; hhalf < 2; hhalf++) {
                const int i = mt * 2 + hhalf;
                const float sx_i = sxr[i];
#pragma unroll
                for (int nt = 0; nt < 2; nt++) {
                    const int c0 = kbw + nt * 8;
                    float v0 = acc[mt][nt][hhalf * 2 + 0];
                    float v1 = acc[mt][nt][hhalf * 2 + 1];
                    float u0 = __fadd_rn(sx_i, sc_sm[c0]);
                    float d0 = __fadd_rn(u0, -__fmul_rn(2.0f, v0));
                    if (d0 < minv[i]) { minv[i] = d0; mink[i] = c0; }
                    float u1 = __fadd_rn(sx_i, sc_sm[c0 + 1]);
                    float d1 = __fadd_rn(u1, -__fmul_rn(2.0f, v1));
                    if (d1 < minv[i]) { minv[i] = d1; mink[i] = c0 + 1; }
                }
            }
        __syncthreads();                        // compute(t) done before buf overwrite
    }

    // ---- cross-lane (groups of 4 share a row), then cross-wn merge ----
    float* fred = (float*)(smem + OFF_RED);
    int*   ired = (int*)(smem + OFF_RED + 1024);
#pragma unroll
    for (int i = 0; i < 4; i++) {
        float v = minv[i]; int id = mink[i];
#pragma unroll
        for (int off = 1; off <= 2; off <<= 1) {
            float ov = __shfl_xor_sync(0xffffffffu, v, off);
            int   oi = __shfl_xor_sync(0xffffffffu, id, off);
            if (ov < v || (ov == v && oi < id)) { v = ov; id = oi; }
        }
        if ((lane & 3) == 0) {
            int r = wm * 32 + i * 8 + (lane >> 2);
            fred[wn * 128 + r] = v;
            ired[wn * 128 + r] = id;
        }
    }
    __syncthreads();
    if (tid < 128) {
        float va = fred[tid], vb = fred[128 + tid];
        int   ia = ired[tid], ib = ired[128 + tid];
        float v = va; int k = ia;
        if (vb < va || (vb == va && ib < ia)) { v = vb; k = ib; }
        unsigned long long pk = ((unsigned long long)__float_as_uint(v) << 32)
                              | (unsigned)(k + kofs);
        atomicMin(&g_best[n0 + tid], pk);
    }
}

// ---------------- idx output + counts (from merged g_best) ----------------
__global__ void k_idxcnt(float* __restrict__ oidx) {
    int t = blockIdx.x * blockDim.x + threadIdx.x;
    int k = (int)(unsigned)(g_best[t] & 0xFFFFFFFFull);
    atomicAdd(&g_counts[k], 1);
    if (oidx) oidx[t] = (float)k;
}

// ---------------- quant gather + loss (smem-transposed, fully coalesced) ----------------
// Block: 32 vectors (one b, 32 hw) x all 256 d.  Grid 2048 x 256 threads.
__global__ void k_out(const float* __restrict__ x, const float* __restrict__ cb,
                      float* __restrict__ outq) {
    __shared__ float q_sm[32][257];
    __shared__ int   kk[32];
    const int tid = threadIdx.x, lane = tid & 31, w = tid >> 5;
    const int b   = blockIdx.x >> 5;
    const int hw0 = (blockIdx.x & 31) << 5;

    if (tid < 32)
        kk[tid] = (int)(unsigned)(g_best[(b << 10) + hw0 + tid] & 0xFFFFFFFFull);
    __syncthreads();

    // load 32 codebook rows, coalesced float4, conflict-free padded smem
    {
        int r = tid >> 3, c4 = (tid & 7) << 2;         // 8 threads/row, float4 each
        const float4* src = (const float4*)(cb + kk[r] * DIM);
#pragma unroll
        for (int j = 0; j < 8; j++) {
            float4 v = __ldg(&src[(c4 >> 2) + j * 8]);
            int c = c4 + j * 32;
            q_sm[r][c + 0] = v.x; q_sm[r][c + 1] = v.y;
            q_sm[r][c + 2] = v.z; q_sm[r][c + 3] = v.w;
        }
    }
    __syncthreads();

    // write out[b][d][hw0+lane] coalesced; accumulate loss
    double ls = 0.0;
    const size_t base = (size_t)b * DIM * HW + hw0 + lane;
#pragma unroll 4
    for (int dd = 0; dd < 32; dd++) {
        int d = w * 32 + dd;
        float q  = q_sm[lane][d];
        size_t e = base + (size_t)d * HW;
        float xv = __ldg(&x[e]);
        outq[e] = q;
        float df = __fadd_rn(q, -xv);
        ls += (double)__fmul_rn(df, df);
    }
    for (int off = 16; off; off >>= 1) ls += __shfl_down_sync(0xffffffffu, ls, off);
    __shared__ double ws[8];
    if (lane == 0) ws[w] = ls;
    __syncthreads();
    if (tid == 0) {
        double s = 0.0;
        for (int i = 0; i < 8; i++) s += ws[i];
        atomicAdd(&g_loss, s);
    }
}

// ---------------- scalars: loss & perplexity ----------------
__global__ void k_fin(float* __restrict__ o_loss, float* __restrict__ o_perp) {
    __shared__ double ws[8];
    int tid = threadIdx.x;
    double s = 0.0;
    for (int k = tid; k < K_CODES; k += 256) {
        float p = (float)g_counts[k] / 65536.0f;
        float l = logf(__fadd_rn(p, 1e-10f));
        s += (double)__fmul_rn(p, l);
    }
    for (int off = 16; off; off >>= 1) s += __shfl_down_sync(0xffffffffu, s, off);
    if ((tid & 31) == 0) ws[tid >> 5] = s;
    __syncthreads();
    if (tid == 0) {
        double tot = 0.0;
        for (int i = 0; i < 8; i++) tot += ws[i];
        *o_perp = expf(-(float)tot);
        float m = (float)(g_loss / (double)QELEMS);
        *o_loss = __fadd_rn(m, __fmul_rn(0.25f, m));
    }
}

// ---------------- launch ----------------
extern "C" void kernel_launch(void* const* d_in, const int* in_sizes, int n_in,
                              void* d_out, int out_size) {
    const float* x  = (const float*)d_in[0];
    const float* cb = (const float*)d_in[1];
    if (n_in >= 2 && in_sizes[0] == K_CODES * DIM && in_sizes[1] == QELEMS) {
        x = (const float*)d_in[1]; cb = (const float*)d_in[0];
    }
    float* out = (float*)d_out;

    float* o_loss  = out;
    float* o_quant = out + 1;
    float* o_perp  = out + 1 + QELEMS;
    float* o_idx   = out + 2 + QELEMS;
    if (out_size == QELEMS) {
        o_quant = out; o_loss = nullptr; o_perp = nullptr; o_idx = nullptr;
    }

    cudaFuncSetAttribute(k_main3, cudaFuncAttributeMaxDynamicSharedMemorySize, SMEM_TOTAL);

    k_init      <<<256,  256>>>();
    k_prep_split<<<2048, 256>>>(cb);
    k_prep_sc   <<<8,    256>>>(cb);
    k_prep_sx   <<<256,  256>>>(x);
    k_main3     <<<1024, 256, SMEM_TOTAL>>>(x);
    k_idxcnt    <<<256,  256>>>(o_idx);
    k_out       <<<2048, 256>>>(x, cb, o_quant);
    if (o_loss) k_fin   <<<1,   256>>>(o_loss, o_perp);
}